// round 15
// baseline (speedup 1.0000x reference)
#include <cuda_runtime.h>
#include <cuda_fp16.h>
#include <cstdint>
#include <math.h>

#define BATCH 256
#define NI    1152
#define NO    10
#define DOUT  16
#define DIN   8
#define OD    160          // NO * DOUT

// ---------------- scratch ----------------
__device__ __half g_xhat[(size_t)BATCH * NI * OD];   // [b][i][od] fp16, 94.5MB

// ---------------- packed fp32x2 helpers (sm_103a) ----------------
typedef unsigned long long ull;
__device__ __forceinline__ ull pack2(float x, float y) {
    ull r; asm("mov.b64 %0, {%1, %2};" : "=l"(r) : "f"(x), "f"(y)); return r;
}
__device__ __forceinline__ float2 unpk2(ull v) {
    float2 r; asm("mov.b64 {%0, %1}, %2;" : "=f"(r.x), "=f"(r.y) : "l"(v)); return r;
}
__device__ __forceinline__ ull ffma2(ull a, ull b, ull c) {
    ull d; asm("fma.rn.f32x2 %0, %1, %2, %3;" : "=l"(d) : "l"(a), "l"(b), "l"(c)); return d;
}

// ---------------- cluster helpers ----------------
__device__ __forceinline__ void cluster_sync_() {
    asm volatile("barrier.cluster.arrive.aligned;" ::: "memory");
    asm volatile("barrier.cluster.wait.aligned;" ::: "memory");
}
__device__ __forceinline__ unsigned int smem_u32(const void* p) {
    unsigned int a;
    asm("{ .reg .u64 t; cvta.to.shared.u64 t, %1; cvt.u32.u64 %0, t; }" : "=r"(a) : "l"(p));
    return a;
}
__device__ __forceinline__ void st_remote_f32x2(unsigned int saddr, unsigned int peer, float2 v) {
    unsigned int ra;
    asm volatile("mapa.shared::cluster.u32 %0, %1, %2;" : "=r"(ra) : "r"(saddr), "r"(peer));
    asm volatile("st.shared::cluster.f32 [%0], %1;"   :: "r"(ra), "f"(v.x) : "memory");
    asm volatile("st.shared::cluster.f32 [%0+4], %1;" :: "r"(ra), "f"(v.y) : "memory");
}

// =====================================================================
// Kernel 1 (stable, ~21us): thread owns (i, od-octet), 64 weight floats
// register-resident across 64 batches, one STG.128 per batch.
// =====================================================================
#define K1_IT 16
#define K1_BT 64

__global__ __launch_bounds__(320) void k1_xhat(const float* __restrict__ x,
                                               const float* __restrict__ w)
{
    __shared__ ull xs2[K1_BT][K1_IT * DIN];   // (x,x) packed, 64KB

    const int i0 = blockIdx.x * K1_IT;
    const int b0 = blockIdx.y * K1_BT;
    const int tid = threadIdx.x;

    for (int u = tid; u < K1_BT * K1_IT * DIN; u += 320) {
        int bl = u >> 7, c128 = u & 127;
        float v = x[(size_t)(b0 + bl) * (NI * DIN) + (size_t)i0 * DIN + c128];
        xs2[bl][c128] = pack2(v, v);
    }

    const int il  = tid / 20;
    const int oct = tid % 20;
    const int i   = i0 + il;
    const int o   = oct >> 1;
    const int d0  = (oct & 1) * 8;

    const float4* wp = (const float4*)&w[(((size_t)o * NI + i) * 16 + d0) * 8];
    float wf[64];
    #pragma unroll
    for (int k = 0; k < 16; k++) ((float4*)wf)[k] = wp[k];
    ull pw[4][8];
    #pragma unroll
    for (int p = 0; p < 4; p++)
        #pragma unroll
        for (int c = 0; c < 8; c++)
            pw[p][c] = pack2(wf[(2 * p) * 8 + c], wf[(2 * p + 1) * 8 + c]);
    __syncthreads();

    const ull* xrow0 = &xs2[0][il * 8];
    #pragma unroll 2
    for (int b = 0; b < K1_BT; b++) {
        const ull* xr = xrow0 + (size_t)b * (K1_IT * DIN);
        ull a0 = 0ull, a1 = 0ull, a2 = 0ull, a3 = 0ull;
        #pragma unroll
        for (int c = 0; c < 8; c++) {
            ull xx = xr[c];
            a0 = ffma2(pw[0][c], xx, a0);
            a1 = ffma2(pw[1][c], xx, a1);
            a2 = ffma2(pw[2][c], xx, a2);
            a3 = ffma2(pw[3][c], xx, a3);
        }
        float2 f0 = unpk2(a0), f1 = unpk2(a1), f2 = unpk2(a2), f3 = unpk2(a3);
        union { __half2 h; unsigned int u; } c0, c1, c2, c3;
        c0.h = __float22half2_rn(f0);
        c1.h = __float22half2_rn(f1);
        c2.h = __float22half2_rn(f2);
        c3.h = __float22half2_rn(f3);
        size_t base = ((size_t)(b0 + b) * NI + i) * OD + 8 * oct;
        *(uint4*)(g_xhat + base) = make_uint4(c0.u, c1.u, c2.u, c3.u);
    }
}

// =====================================================================
// Kernel 2: fused routing, 4-CTA cluster per batch (288 rows/CTA),
// 384 threads/CTA, 2 CTAs/SM. LDG copy FUSED with s0 accumulation;
// shfl-free p1/p2; half2 acc; pair-wise double-buffered DSMEM exchange;
// register t-pair epilogue.
// =====================================================================
#define K2_THREADS 384
#define CLS   4
#define NIH   288             // i-rows per CTA
#define ROWB  336             // padded row stride (21 x 16B)
#define NCH_P2 9              // p2 chunks: 360 thr, 32 rows each

// dynamic smem layout (bytes) — all 16B-aligned
#define XH_OFF    0
#define XH_SZ     (NIH * ROWB)                 // 96,768
#define SH_OFF    (XH_OFF + XH_SZ)             // shared: s0pacc_h [16][160] fp16 (early)
#define SH_SZ     (NIH * NO * 2)               //         / cbuf [288][10] fp16 (late) = 5,760
#define P2_OFF    (SH_OFF + SH_SZ)             // [9][160] f32
#define P2_SZ     (NCH_P2 * OD * 4)            // 5,760
#define SLOT0_OFF (P2_OFF + P2_SZ)             // [4][160] f32
#define SLOT_SZ   (CLS * OD * 4)               // 2,560
#define SLOT1_OFF (SLOT0_OFF + SLOT_SZ)
#define TH2_OFF   (SLOT1_OFF + SLOT_SZ)        // [80] half2
#define TH2_SZ    320
#define K2_SMEM   (TH2_OFF + TH2_SZ)           // 113,728 B (x2 per SM)

__global__ __cluster_dims__(CLS, 1, 1) __launch_bounds__(K2_THREADS, 2)
void k2_route(float* __restrict__ dout)
{
    extern __shared__ __align__(16) char sm[];
    char*    xhb  = sm + XH_OFF;
    __half*  cbuf = (__half*)(sm + SH_OFF);     // alive from p1 on
    char*    s0p  = sm + SH_OFF;                // alias: alive until exchange 0
    float*   pacc = (float*)(sm + P2_OFF);
    __half2* th2  = (__half2*)(sm + TH2_OFF);

    const int cta = blockIdx.x;
    const int b   = cta >> 2;
    const unsigned int rank = cta & 3;
    const int tid = threadIdx.x;
    const int q   = tid % 40;     // od-quad (p2)
    const int o_q = q >> 2;

    const unsigned int sqmask = (tid < 64) ? 0xffffffffu : 0x0000ffffu;
    float2 t2 = make_float2(0.f, 0.f);   // register-resident t pair (tid<80)

    const __half* gsrc = g_xhat + ((size_t)b * NI + (size_t)rank * NIH) * OD;

    // ---- fused copy + s0: thread owns fixed od-octet u, rows r0+16k ----
    if (tid < 320) {
        const int u  = tid % 20;
        const int r0 = tid / 20;
        float fa[8];
        #pragma unroll
        for (int e = 0; e < 8; e++) fa[e] = 0.f;

        #pragma unroll
        for (int kb = 0; kb < 6; kb++) {
            uint4 v0 = *(const uint4*)(gsrc + (size_t)(tid + (kb * 3 + 0) * 320) * 8);
            uint4 v1 = *(const uint4*)(gsrc + (size_t)(tid + (kb * 3 + 1) * 320) * 8);
            uint4 v2 = *(const uint4*)(gsrc + (size_t)(tid + (kb * 3 + 2) * 320) * 8);
            // stage into smem (padded rows)
            const int rowA = r0 + 16 * (kb * 3 + 0);
            const int rowB = r0 + 16 * (kb * 3 + 1);
            const int rowC = r0 + 16 * (kb * 3 + 2);
            *(uint4*)(xhb + rowA * ROWB + u * 16) = v0;
            *(uint4*)(xhb + rowB * ROWB + u * 16) = v1;
            *(uint4*)(xhb + rowC * ROWB + u * 16) = v2;
            // accumulate 3 rows in half2, flush to fp32
            __half2 a0 = __hadd2(__hadd2(*(__half2*)&v0.x, *(__half2*)&v1.x), *(__half2*)&v2.x);
            __half2 a1 = __hadd2(__hadd2(*(__half2*)&v0.y, *(__half2*)&v1.y), *(__half2*)&v2.y);
            __half2 a2 = __hadd2(__hadd2(*(__half2*)&v0.z, *(__half2*)&v1.z), *(__half2*)&v2.z);
            __half2 a3 = __hadd2(__hadd2(*(__half2*)&v0.w, *(__half2*)&v1.w), *(__half2*)&v2.w);
            float2 f0 = __half22float2(a0), f1 = __half22float2(a1);
            float2 f2 = __half22float2(a2), f3 = __half22float2(a3);
            fa[0] += f0.x; fa[1] += f0.y; fa[2] += f1.x; fa[3] += f1.y;
            fa[4] += f2.x; fa[5] += f2.y; fa[6] += f3.x; fa[7] += f3.y;
        }
        // store s0 partial as 4 half2 -> s0p[r0][u-octet]
        union { __half2 h; unsigned int u32; } p0, p1, p2, p3;
        p0.h = __floats2half2_rn(fa[0], fa[1]);
        p1.h = __floats2half2_rn(fa[2], fa[3]);
        p2.h = __floats2half2_rn(fa[4], fa[5]);
        p3.h = __floats2half2_rn(fa[6], fa[7]);
        *(uint4*)(s0p + r0 * 320 + u * 16) = make_uint4(p0.u32, p1.u32, p2.u32, p3.u32);
    }
    __syncthreads();

    // ---- exchange 0 (buf0): s0; squash pairs -> t2 regs + th2 ----
    {
        float* slot = (float*)(sm + SLOT0_OFF);
        if (tid < 80) {
            float2 pv = make_float2(0.f, 0.f);
            #pragma unroll
            for (int r = 0; r < 16; r++) {
                __half2 h = *(__half2*)(s0p + r * 320 + tid * 4);
                float2 f = __half22float2(h);
                pv.x += f.x; pv.y += f.y;
            }
            *(float2*)&slot[rank * OD + 2 * tid] = pv;
            unsigned int sa = smem_u32(&slot[rank * OD + 2 * tid]);
            #pragma unroll
            for (int r = 1; r < CLS; r++) st_remote_f32x2(sa, rank ^ r, pv);
        }
        cluster_sync_();
        if (tid < 80) {
            float sa = 0.f, sb = 0.f;
            #pragma unroll
            for (int rr = 0; rr < CLS; rr++) {
                float2 s = *(const float2*)&slot[rr * OD + 2 * tid];
                sa += s.x; sb += s.y;
            }
            sa *= 0.1f; sb *= 0.1f;
            float v = sa * sa + sb * sb;
            v += __shfl_xor_sync(sqmask, v, 4);
            v += __shfl_xor_sync(sqmask, v, 2);
            v += __shfl_xor_sync(sqmask, v, 1);
            float sc = (v / (1.0f + v)) / (sqrtf(v) + 1e-8f);
            t2.x = sa * sc; t2.y = sb * sc;
            th2[tid] = __floats2half2_rn(t2.x, t2.y);
        }
    }
    __syncthreads();

    // ---- two routing passes ----
    #pragma unroll 1
    for (int pass = 0; pass < 2; pass++) {
        // ===== phase 1: thread = one i (288 threads); half2 dots + softmax
        if (tid < NIH) {
            const char* row = xhb + tid * ROWB;
            float e[NO];
            #pragma unroll
            for (int o = 0; o < NO; o++) {
                uint4 xa = *(const uint4*)(row + o * 32);
                uint4 xb = *(const uint4*)(row + o * 32 + 16);
                uint4 ta = *(const uint4*)((const char*)th2 + o * 32);
                uint4 tb = *(const uint4*)((const char*)th2 + o * 32 + 16);
                __half2 acc = __hmul2(*(__half2*)&xa.x, *(__half2*)&ta.x);
                acc = __hfma2(*(__half2*)&xa.y, *(__half2*)&ta.y, acc);
                acc = __hfma2(*(__half2*)&xa.z, *(__half2*)&ta.z, acc);
                acc = __hfma2(*(__half2*)&xa.w, *(__half2*)&ta.w, acc);
                acc = __hfma2(*(__half2*)&xb.x, *(__half2*)&tb.x, acc);
                acc = __hfma2(*(__half2*)&xb.y, *(__half2*)&tb.y, acc);
                acc = __hfma2(*(__half2*)&xb.z, *(__half2*)&tb.z, acc);
                acc = __hfma2(*(__half2*)&xb.w, *(__half2*)&tb.w, acc);
                float2 f = __half22float2(acc);
                e[o] = f.x + f.y;
            }
            float m = e[0];
            #pragma unroll
            for (int o = 1; o < NO; o++) m = fmaxf(m, e[o]);
            float sum = 0.f;
            #pragma unroll
            for (int o = 0; o < NO; o++) { e[o] = __expf(e[o] - m); sum += e[o]; }
            const float inv = 1.0f / sum;
            __half2* cp = (__half2*)(cbuf + tid * NO);
            #pragma unroll
            for (int p = 0; p < 5; p++)
                cp[p] = __floats2half2_rn(e[2 * p] * inv, e[2 * p + 1] * inv);
        }
        __syncthreads();

        // ===== phase 2: thread = (ch, quad); half2 acc of c*xh, flush/4
        if (tid < NCH_P2 * 40) {
            const int ch = tid / 40;
            float4 pa = make_float4(0.f, 0.f, 0.f, 0.f);
            #pragma unroll
            for (int g4 = 0; g4 < 8; g4++) {
                __half2 a01 = __float2half2_rn(0.f), a23 = __float2half2_rn(0.f);
                #pragma unroll
                for (int kk = 0; kk < 4; kk++) {
                    const int row = ch * 32 + g4 * 4 + kk;
                    uint2 v = *(const uint2*)(xhb + row * ROWB + q * 8);
                    __half2 c2 = __half2half2(cbuf[row * NO + o_q]);
                    a01 = __hfma2(*(__half2*)&v.x, c2, a01);
                    a23 = __hfma2(*(__half2*)&v.y, c2, a23);
                }
                float2 f01 = __half22float2(a01), f23 = __half22float2(a23);
                pa.x += f01.x; pa.y += f01.y; pa.z += f23.x; pa.w += f23.y;
            }
            *(float4*)&pacc[ch * OD + q * 4] = pa;
        }
        __syncthreads();

        // ===== exchange (alternating buffer) + squash pairs
        {
            float* slot = (float*)(sm + ((pass == 0) ? SLOT1_OFF : SLOT0_OFF));
            if (tid < 80) {
                float2 pv = make_float2(0.f, 0.f);
                #pragma unroll
                for (int c2 = 0; c2 < NCH_P2; c2++) {
                    float2 t = *(const float2*)&pacc[c2 * OD + 2 * tid];
                    pv.x += t.x; pv.y += t.y;
                }
                *(float2*)&slot[rank * OD + 2 * tid] = pv;
                unsigned int sa = smem_u32(&slot[rank * OD + 2 * tid]);
                #pragma unroll
                for (int r = 1; r < CLS; r++) st_remote_f32x2(sa, rank ^ r, pv);
            }
            cluster_sync_();
            if (tid < 80) {
                float sa = 0.f, sb = 0.f;
                #pragma unroll
                for (int rr = 0; rr < CLS; rr++) {
                    float2 s = *(const float2*)&slot[rr * OD + 2 * tid];
                    sa += s.x; sb += s.y;
                }
                float v = sa * sa + sb * sb;
                v += __shfl_xor_sync(sqmask, v, 4);
                v += __shfl_xor_sync(sqmask, v, 2);
                v += __shfl_xor_sync(sqmask, v, 1);
                float sc = (v / (1.0f + v)) / (sqrtf(v) + 1e-8f);
                if (pass == 0) {
                    t2.x += sa * sc; t2.y += sb * sc;        // t = out0 + out1
                    th2[tid] = __floats2half2_rn(t2.x, t2.y);
                } else if (rank == 0) {
                    *(float2*)&dout[b * OD + 2 * tid] = make_float2(sa * sc, sb * sc);
                }
            }
        }
        __syncthreads();
    }
}

// =====================================================================
extern "C" void kernel_launch(void* const* d_in, const int* in_sizes, int n_in,
                              void* d_out, int out_size)
{
    const float* x = (const float*)d_in[0];   // [256,1152,8]
    const float* w = (const float*)d_in[1];   // [10,1152,16,8]
    float* out = (float*)d_out;               // [256,10,16]

    cudaFuncSetAttribute(k2_route, cudaFuncAttributeMaxDynamicSharedMemorySize, K2_SMEM);

    k1_xhat<<<dim3(NI / K1_IT, BATCH / K1_BT), 320>>>(x, w);
    k2_route<<<CLS * BATCH, K2_THREADS, K2_SMEM>>>(out);
}

// round 16
// speedup vs baseline: 1.0473x; 1.0473x over previous
#include <cuda_runtime.h>
#include <cuda_fp16.h>
#include <cstdint>
#include <math.h>

#define BATCH 256
#define NI    1152
#define NO    10
#define DOUT  16
#define DIN   8
#define OD    160          // NO * DOUT

// ---------------- scratch ----------------
__device__ __half g_xhat[(size_t)BATCH * NI * OD];   // [b][i][od] fp16, 94.5MB

// ---------------- packed fp32x2 helpers (sm_103a) ----------------
typedef unsigned long long ull;
__device__ __forceinline__ ull pack2(float x, float y) {
    ull r; asm("mov.b64 %0, {%1, %2};" : "=l"(r) : "f"(x), "f"(y)); return r;
}
__device__ __forceinline__ float2 unpk2(ull v) {
    float2 r; asm("mov.b64 {%0, %1}, %2;" : "=f"(r.x), "=f"(r.y) : "l"(v)); return r;
}
__device__ __forceinline__ ull ffma2(ull a, ull b, ull c) {
    ull d; asm("fma.rn.f32x2 %0, %1, %2, %3;" : "=l"(d) : "l"(a), "l"(b), "l"(c)); return d;
}

// ---------------- cluster / async helpers ----------------
__device__ __forceinline__ void cluster_sync_() {
    asm volatile("barrier.cluster.arrive.aligned;" ::: "memory");
    asm volatile("barrier.cluster.wait.aligned;" ::: "memory");
}
__device__ __forceinline__ unsigned int smem_u32(const void* p) {
    unsigned int a;
    asm("{ .reg .u64 t; cvta.to.shared.u64 t, %1; cvt.u32.u64 %0, t; }" : "=r"(a) : "l"(p));
    return a;
}
__device__ __forceinline__ void st_remote_f32x2(unsigned int saddr, unsigned int peer, float2 v) {
    unsigned int ra;
    asm volatile("mapa.shared::cluster.u32 %0, %1, %2;" : "=r"(ra) : "r"(saddr), "r"(peer));
    asm volatile("st.shared::cluster.f32 [%0], %1;"   :: "r"(ra), "f"(v.x) : "memory");
    asm volatile("st.shared::cluster.f32 [%0+4], %1;" :: "r"(ra), "f"(v.y) : "memory");
}
__device__ __forceinline__ void cp_async16(unsigned int sdst, const void* gsrc) {
    asm volatile("cp.async.cg.shared.global [%0], [%1], 16;" :: "r"(sdst), "l"(gsrc) : "memory");
}

// =====================================================================
// Kernel 1 (stable, ~21us): thread owns (i, od-octet), 64 weight floats
// register-resident across 64 batches, one STG.128 per batch.
// =====================================================================
#define K1_IT 16
#define K1_BT 64

__global__ __launch_bounds__(320) void k1_xhat(const float* __restrict__ x,
                                               const float* __restrict__ w)
{
    __shared__ ull xs2[K1_BT][K1_IT * DIN];   // (x,x) packed, 64KB

    const int i0 = blockIdx.x * K1_IT;
    const int b0 = blockIdx.y * K1_BT;
    const int tid = threadIdx.x;

    for (int u = tid; u < K1_BT * K1_IT * DIN; u += 320) {
        int bl = u >> 7, c128 = u & 127;
        float v = x[(size_t)(b0 + bl) * (NI * DIN) + (size_t)i0 * DIN + c128];
        xs2[bl][c128] = pack2(v, v);
    }

    const int il  = tid / 20;
    const int oct = tid % 20;
    const int i   = i0 + il;
    const int o   = oct >> 1;
    const int d0  = (oct & 1) * 8;

    const float4* wp = (const float4*)&w[(((size_t)o * NI + i) * 16 + d0) * 8];
    float wf[64];
    #pragma unroll
    for (int k = 0; k < 16; k++) ((float4*)wf)[k] = wp[k];
    ull pw[4][8];
    #pragma unroll
    for (int p = 0; p < 4; p++)
        #pragma unroll
        for (int c = 0; c < 8; c++)
            pw[p][c] = pack2(wf[(2 * p) * 8 + c], wf[(2 * p + 1) * 8 + c]);
    __syncthreads();

    const ull* xrow0 = &xs2[0][il * 8];
    #pragma unroll 2
    for (int b = 0; b < K1_BT; b++) {
        const ull* xr = xrow0 + (size_t)b * (K1_IT * DIN);
        ull a0 = 0ull, a1 = 0ull, a2 = 0ull, a3 = 0ull;
        #pragma unroll
        for (int c = 0; c < 8; c++) {
            ull xx = xr[c];
            a0 = ffma2(pw[0][c], xx, a0);
            a1 = ffma2(pw[1][c], xx, a1);
            a2 = ffma2(pw[2][c], xx, a2);
            a3 = ffma2(pw[3][c], xx, a3);
        }
        float2 f0 = unpk2(a0), f1 = unpk2(a1), f2 = unpk2(a2), f3 = unpk2(a3);
        union { __half2 h; unsigned int u; } c0, c1, c2, c3;
        c0.h = __float22half2_rn(f0);
        c1.h = __float22half2_rn(f1);
        c2.h = __float22half2_rn(f2);
        c3.h = __float22half2_rn(f3);
        size_t base = ((size_t)(b0 + b) * NI + i) * OD + 8 * oct;
        *(uint4*)(g_xhat + base) = make_uint4(c0.u, c1.u, c2.u, c3.u);
    }
}

// =====================================================================
// Kernel 2: fused routing, 4-CTA cluster per batch (288 rows/CTA),
// 384 threads/CTA, 2 CTAs/SM. Self-mapped cp.async copy: thread owns a
// fixed od-octet + 18 rows; s0 accumulates ONLY self-copied rows after
// each wait_group (no cross-thread syncs). Shfl-free p1/p2; half2 acc;
// pair-wise double-buffered DSMEM exchange; register t-pair epilogue.
// =====================================================================
#define K2_THREADS 384
#define CLS   4
#define NIH   288             // i-rows per CTA
#define ROWB  336             // padded row stride (21 x 16B)
#define NCH_P2 9              // p2 chunks: 360 thr, 32 rows each

// dynamic smem layout (bytes) — all 16B-aligned
#define XH_OFF    0
#define XH_SZ     (NIH * ROWB)                 // 96,768
#define SH_OFF    (XH_OFF + XH_SZ)             // s0p [16][160] fp16 (early) / cbuf [288][10] fp16 (late)
#define SH_SZ     (NIH * NO * 2)               // 5,760
#define P2_OFF    (SH_OFF + SH_SZ)             // [9][160] f32
#define P2_SZ     (NCH_P2 * OD * 4)            // 5,760
#define SLOT0_OFF (P2_OFF + P2_SZ)             // [4][160] f32
#define SLOT_SZ   (CLS * OD * 4)               // 2,560
#define SLOT1_OFF (SLOT0_OFF + SLOT_SZ)
#define TH2_OFF   (SLOT1_OFF + SLOT_SZ)        // [80] half2
#define TH2_SZ    320
#define K2_SMEM   (TH2_OFF + TH2_SZ)           // 113,728 B (x2 per SM)

__global__ __cluster_dims__(CLS, 1, 1) __launch_bounds__(K2_THREADS, 2)
void k2_route(float* __restrict__ dout)
{
    extern __shared__ __align__(16) char sm[];
    char*    xhb  = sm + XH_OFF;
    __half*  cbuf = (__half*)(sm + SH_OFF);     // alive from p1 on
    char*    s0p  = sm + SH_OFF;                // alias: alive until exchange 0
    float*   pacc = (float*)(sm + P2_OFF);
    __half2* th2  = (__half2*)(sm + TH2_OFF);

    const int cta = blockIdx.x;
    const int b   = cta >> 2;
    const unsigned int rank = cta & 3;
    const int tid = threadIdx.x;
    const int q   = tid % 40;     // od-quad (p2)
    const int o_q = q >> 2;

    const unsigned int sqmask = (tid < 64) ? 0xffffffffu : 0x0000ffffu;
    float2 t2 = make_float2(0.f, 0.f);   // register-resident t pair (tid<80)

    const __half* gsrc = g_xhat + ((size_t)b * NI + (size_t)rank * NIH) * OD;
    const unsigned int xh_s = smem_u32(xhb);

    // ---- self-mapped async copy + s0 (320 threads own (octet u, rows r0+16k))
    {
        const int u  = tid % 20;
        const int r0 = tid / 20;          // 0..15 for tid<320
        const bool act = (tid < 320);

        // issue 18 cp.async in 3 groups of 6 (rows r0+16k, fixed octet u)
        #pragma unroll
        for (int g = 0; g < 3; g++) {
            if (act) {
                #pragma unroll
                for (int t = 0; t < 6; t++) {
                    const int row = r0 + 16 * (g * 6 + t);
                    cp_async16(xh_s + row * ROWB + u * 16,
                               gsrc + (size_t)row * OD + u * 8);
                }
            }
            asm volatile("cp.async.commit_group;" ::: "memory");
        }

        // accumulate own rows per group (no __syncthreads needed)
        float fa[8];
        #pragma unroll
        for (int e = 0; e < 8; e++) fa[e] = 0.f;

        #pragma unroll
        for (int g = 0; g < 3; g++) {
            if (g == 0)      asm volatile("cp.async.wait_group 2;" ::: "memory");
            else if (g == 1) asm volatile("cp.async.wait_group 1;" ::: "memory");
            else             asm volatile("cp.async.wait_group 0;" ::: "memory");
            if (act) {
                #pragma unroll
                for (int h3 = 0; h3 < 2; h3++) {       // 6 rows = 2 x 3, flush per 3
                    __half2 a0 = __float2half2_rn(0.f), a1 = a0, a2 = a0, a3 = a0;
                    #pragma unroll
                    for (int kk = 0; kk < 3; kk++) {
                        const int row = r0 + 16 * (g * 6 + h3 * 3 + kk);
                        uint4 v = *(const uint4*)(xhb + row * ROWB + u * 16);
                        a0 = __hadd2(a0, *(__half2*)&v.x);
                        a1 = __hadd2(a1, *(__half2*)&v.y);
                        a2 = __hadd2(a2, *(__half2*)&v.z);
                        a3 = __hadd2(a3, *(__half2*)&v.w);
                    }
                    float2 f0 = __half22float2(a0), f1 = __half22float2(a1);
                    float2 f2 = __half22float2(a2), f3 = __half22float2(a3);
                    fa[0] += f0.x; fa[1] += f0.y; fa[2] += f1.x; fa[3] += f1.y;
                    fa[4] += f2.x; fa[5] += f2.y; fa[6] += f3.x; fa[7] += f3.y;
                }
            }
        }
        if (act) {
            union { __half2 h; unsigned int u32; } p0, p1, p2, p3;
            p0.h = __floats2half2_rn(fa[0], fa[1]);
            p1.h = __floats2half2_rn(fa[2], fa[3]);
            p2.h = __floats2half2_rn(fa[4], fa[5]);
            p3.h = __floats2half2_rn(fa[6], fa[7]);
            *(uint4*)(s0p + r0 * 320 + u * 16) = make_uint4(p0.u32, p1.u32, p2.u32, p3.u32);
        }
    }
    __syncthreads();

    // ---- exchange 0 (buf0): s0; squash pairs -> t2 regs + th2 ----
    {
        float* slot = (float*)(sm + SLOT0_OFF);
        if (tid < 80) {
            float2 pv = make_float2(0.f, 0.f);
            #pragma unroll
            for (int r = 0; r < 16; r++) {
                __half2 h = *(__half2*)(s0p + r * 320 + tid * 4);
                float2 f = __half22float2(h);
                pv.x += f.x; pv.y += f.y;
            }
            *(float2*)&slot[rank * OD + 2 * tid] = pv;
            unsigned int sa = smem_u32(&slot[rank * OD + 2 * tid]);
            #pragma unroll
            for (int r = 1; r < CLS; r++) st_remote_f32x2(sa, rank ^ r, pv);
        }
        cluster_sync_();
        if (tid < 80) {
            float sa = 0.f, sb = 0.f;
            #pragma unroll
            for (int rr = 0; rr < CLS; rr++) {
                float2 s = *(const float2*)&slot[rr * OD + 2 * tid];
                sa += s.x; sb += s.y;
            }
            sa *= 0.1f; sb *= 0.1f;
            float v = sa * sa + sb * sb;
            v += __shfl_xor_sync(sqmask, v, 4);
            v += __shfl_xor_sync(sqmask, v, 2);
            v += __shfl_xor_sync(sqmask, v, 1);
            float sc = (v / (1.0f + v)) / (sqrtf(v) + 1e-8f);
            t2.x = sa * sc; t2.y = sb * sc;
            th2[tid] = __floats2half2_rn(t2.x, t2.y);
        }
    }
    __syncthreads();

    // ---- two routing passes ----
    #pragma unroll 1
    for (int pass = 0; pass < 2; pass++) {
        // ===== phase 1: thread = one i (288 threads); half2 dots + softmax
        if (tid < NIH) {
            const char* row = xhb + tid * ROWB;
            float e[NO];
            #pragma unroll
            for (int o = 0; o < NO; o++) {
                uint4 xa = *(const uint4*)(row + o * 32);
                uint4 xb = *(const uint4*)(row + o * 32 + 16);
                uint4 ta = *(const uint4*)((const char*)th2 + o * 32);
                uint4 tb = *(const uint4*)((const char*)th2 + o * 32 + 16);
                __half2 acc = __hmul2(*(__half2*)&xa.x, *(__half2*)&ta.x);
                acc = __hfma2(*(__half2*)&xa.y, *(__half2*)&ta.y, acc);
                acc = __hfma2(*(__half2*)&xa.z, *(__half2*)&ta.z, acc);
                acc = __hfma2(*(__half2*)&xa.w, *(__half2*)&ta.w, acc);
                acc = __hfma2(*(__half2*)&xb.x, *(__half2*)&tb.x, acc);
                acc = __hfma2(*(__half2*)&xb.y, *(__half2*)&tb.y, acc);
                acc = __hfma2(*(__half2*)&xb.z, *(__half2*)&tb.z, acc);
                acc = __hfma2(*(__half2*)&xb.w, *(__half2*)&tb.w, acc);
                float2 f = __half22float2(acc);
                e[o] = f.x + f.y;
            }
            float m = e[0];
            #pragma unroll
            for (int o = 1; o < NO; o++) m = fmaxf(m, e[o]);
            float sum = 0.f;
            #pragma unroll
            for (int o = 0; o < NO; o++) { e[o] = __expf(e[o] - m); sum += e[o]; }
            const float inv = 1.0f / sum;
            __half2* cp = (__half2*)(cbuf + tid * NO);
            #pragma unroll
            for (int p = 0; p < 5; p++)
                cp[p] = __floats2half2_rn(e[2 * p] * inv, e[2 * p + 1] * inv);
        }
        __syncthreads();

        // ===== phase 2: thread = (ch, quad); half2 acc of c*xh, flush/4
        if (tid < NCH_P2 * 40) {
            const int ch = tid / 40;
            float4 pa = make_float4(0.f, 0.f, 0.f, 0.f);
            #pragma unroll
            for (int g4 = 0; g4 < 8; g4++) {
                __half2 a01 = __float2half2_rn(0.f), a23 = __float2half2_rn(0.f);
                #pragma unroll
                for (int kk = 0; kk < 4; kk++) {
                    const int row = ch * 32 + g4 * 4 + kk;
                    uint2 v = *(const uint2*)(xhb + row * ROWB + q * 8);
                    __half2 c2 = __half2half2(cbuf[row * NO + o_q]);
                    a01 = __hfma2(*(__half2*)&v.x, c2, a01);
                    a23 = __hfma2(*(__half2*)&v.y, c2, a23);
                }
                float2 f01 = __half22float2(a01), f23 = __half22float2(a23);
                pa.x += f01.x; pa.y += f01.y; pa.z += f23.x; pa.w += f23.y;
            }
            *(float4*)&pacc[ch * OD + q * 4] = pa;
        }
        __syncthreads();

        // ===== exchange (alternating buffer) + squash pairs
        {
            float* slot = (float*)(sm + ((pass == 0) ? SLOT1_OFF : SLOT0_OFF));
            if (tid < 80) {
                float2 pv = make_float2(0.f, 0.f);
                #pragma unroll
                for (int c2 = 0; c2 < NCH_P2; c2++) {
                    float2 t = *(const float2*)&pacc[c2 * OD + 2 * tid];
                    pv.x += t.x; pv.y += t.y;
                }
                *(float2*)&slot[rank * OD + 2 * tid] = pv;
                unsigned int sa = smem_u32(&slot[rank * OD + 2 * tid]);
                #pragma unroll
                for (int r = 1; r < CLS; r++) st_remote_f32x2(sa, rank ^ r, pv);
            }
            cluster_sync_();
            if (tid < 80) {
                float sa = 0.f, sb = 0.f;
                #pragma unroll
                for (int rr = 0; rr < CLS; rr++) {
                    float2 s = *(const float2*)&slot[rr * OD + 2 * tid];
                    sa += s.x; sb += s.y;
                }
                float v = sa * sa + sb * sb;
                v += __shfl_xor_sync(sqmask, v, 4);
                v += __shfl_xor_sync(sqmask, v, 2);
                v += __shfl_xor_sync(sqmask, v, 1);
                float sc = (v / (1.0f + v)) / (sqrtf(v) + 1e-8f);
                if (pass == 0) {
                    t2.x += sa * sc; t2.y += sb * sc;        // t = out0 + out1
                    th2[tid] = __floats2half2_rn(t2.x, t2.y);
                } else if (rank == 0) {
                    *(float2*)&dout[b * OD + 2 * tid] = make_float2(sa * sc, sb * sc);
                }
            }
        }
        __syncthreads();
    }
}

// =====================================================================
extern "C" void kernel_launch(void* const* d_in, const int* in_sizes, int n_in,
                              void* d_out, int out_size)
{
    const float* x = (const float*)d_in[0];   // [256,1152,8]
    const float* w = (const float*)d_in[1];   // [10,1152,16,8]
    float* out = (float*)d_out;               // [256,10,16]

    cudaFuncSetAttribute(k2_route, cudaFuncAttributeMaxDynamicSharedMemorySize, K2_SMEM);

    k1_xhat<<<dim3(NI / K1_IT, BATCH / K1_BT), 320>>>(x, w);
    k2_route<<<CLS * BATCH, K2_THREADS, K2_SMEM>>>(out);
}